// round 8
// baseline (speedup 1.0000x reference)
#include <cuda_runtime.h>

#define TT 64
#define BB 256
#define DD 512

// pre-activations, t-major: g_pre[row][gate][q], row = t*BB+b
__device__ __align__(16) float g_pre[TT * BB * 24];

// ---------------------------------------------------------------------------
// K1: pre[row][j] = X[row,:] @ W*[:, j] + bias[j],  j = gate*6+q (24 outputs)
// grid 128 x 128, one row per thread (24 acc chains). X streamed through a
// double-buffered SMEM tile (128 rows x 16 d, coalesced nL=8 loads, prefetch
// issued before compute so FFMA hides DRAM latency). W staged in two 24KB
// halves [dd][24], read via 6x LDS.128 broadcast. One sync per tile.
// ---------------------------------------------------------------------------
__global__ void __launch_bounds__(128, 1) k1_gemm(
    const float* __restrict__ X,
    const float* __restrict__ Wf, const float* __restrict__ bf,
    const float* __restrict__ Wi, const float* __restrict__ bi,
    const float* __restrict__ Wu, const float* __restrict__ bu,
    const float* __restrict__ Wo, const float* __restrict__ bo,
    const float* __restrict__ thf, const float* __restrict__ thi,
    const float* __restrict__ thu, const float* __restrict__ tho)
{
    __shared__ __align__(16) float Wph[256 * 24];      // W half [dd][24], 24KB
    __shared__ __align__(16) float Xsh[2][128 * 20];   // tile [row][16d+pad], 2x10KB
    __shared__ float Bsh[24];

    const int tid     = threadIdx.x;
    const int rowbase = blockIdx.x << 7;
    const int r0      = tid >> 2;       // staging row base (0..31)
    const int dp      = tid & 3;        // staging float4 within 16d

    if (tid < 24) {
        const int g = tid / 6, q = tid - 6 * (tid / 6);
        const float* bg = (g == 0) ? bf  : (g == 1) ? bi  : (g == 2) ? bu  : bo;
        const float* tg = (g == 0) ? thf : (g == 1) ? thi : (g == 2) ? thu : tho;
        Bsh[tid] = bg[q] + tg[q];
    }

    // stage X tile 0 directly (prologue; latency exposed once)
    {
        const float4* xb = reinterpret_cast<const float4*>(X);
#pragma unroll
        for (int j = 0; j < 4; j++) {
            const int r = r0 + (j << 5);
            float4 v = __ldg(xb + (size_t)(rowbase + r) * 128 + dp);
            *reinterpret_cast<float4*>(&Xsh[0][r * 20 + (dp << 2)]) = v;
        }
    }

    float acc[24];

    for (int kh = 0; kh < 2; kh++) {
        __syncthreads();               // prior readers of Wph done
        // stage W half kh: Wph[dd*24 + g*6+q] = Wg[(kh*256+dd)*6+q]
#pragma unroll
        for (int k = 0; k < 48; k++) {
            int idx = tid + (k << 7);  // 0..6143
            int dd  = idx / 24;
            int col = idx - dd * 24;
            int g2  = col / 6;
            int q2  = col - g2 * 6;
            const float* Ws = (g2 == 0) ? Wf : (g2 == 1) ? Wi : (g2 == 2) ? Wu : Wo;
            Wph[idx] = Ws[((kh << 8) + dd) * 6 + q2];
        }
        __syncthreads();               // Wph (+ initial Xsh) visible

        if (kh == 0) {
#pragma unroll
            for (int j = 0; j < 24; j++) acc[j] = Bsh[j];
        }

        for (int lt = 0; lt < 16; lt++) {
            const int gt  = (kh << 4) + lt;
            const int cur = gt & 1;

            // prefetch next tile's X into regs (LDG issued before compute)
            float4 xs0, xs1, xs2, xs3;
            const bool pf = (gt < 31);
            if (pf) {
                const float4* xb = reinterpret_cast<const float4*>(X) + (size_t)(gt + 1) * 4 + dp;
                xs0 = __ldg(xb + (size_t)(rowbase + r0 +  0) * 128);
                xs1 = __ldg(xb + (size_t)(rowbase + r0 + 32) * 128);
                xs2 = __ldg(xb + (size_t)(rowbase + r0 + 64) * 128);
                xs3 = __ldg(xb + (size_t)(rowbase + r0 + 96) * 128);
            }

            // compute this tile: 16 dd x 24 FFMA
            const float* xr = Xsh[cur] + tid * 20;
#pragma unroll
            for (int dg = 0; dg < 4; dg++) {
                const float4 xv = *reinterpret_cast<const float4*>(xr + (dg << 2));
#pragma unroll
                for (int k = 0; k < 4; k++) {
                    const float xk = (k == 0) ? xv.x : (k == 1) ? xv.y : (k == 2) ? xv.z : xv.w;
                    const float4* wr = reinterpret_cast<const float4*>(
                        Wph + ((lt << 4) + (dg << 2) + k) * 24);
                    const float4 w0 = wr[0], w1 = wr[1], w2 = wr[2];
                    const float4 w3 = wr[3], w4 = wr[4], w5 = wr[5];
                    acc[ 0] = fmaf(xk, w0.x, acc[ 0]);
                    acc[ 1] = fmaf(xk, w0.y, acc[ 1]);
                    acc[ 2] = fmaf(xk, w0.z, acc[ 2]);
                    acc[ 3] = fmaf(xk, w0.w, acc[ 3]);
                    acc[ 4] = fmaf(xk, w1.x, acc[ 4]);
                    acc[ 5] = fmaf(xk, w1.y, acc[ 5]);
                    acc[ 6] = fmaf(xk, w1.z, acc[ 6]);
                    acc[ 7] = fmaf(xk, w1.w, acc[ 7]);
                    acc[ 8] = fmaf(xk, w2.x, acc[ 8]);
                    acc[ 9] = fmaf(xk, w2.y, acc[ 9]);
                    acc[10] = fmaf(xk, w2.z, acc[10]);
                    acc[11] = fmaf(xk, w2.w, acc[11]);
                    acc[12] = fmaf(xk, w3.x, acc[12]);
                    acc[13] = fmaf(xk, w3.y, acc[13]);
                    acc[14] = fmaf(xk, w3.z, acc[14]);
                    acc[15] = fmaf(xk, w3.w, acc[15]);
                    acc[16] = fmaf(xk, w4.x, acc[16]);
                    acc[17] = fmaf(xk, w4.y, acc[17]);
                    acc[18] = fmaf(xk, w4.z, acc[18]);
                    acc[19] = fmaf(xk, w4.w, acc[19]);
                    acc[20] = fmaf(xk, w5.x, acc[20]);
                    acc[21] = fmaf(xk, w5.y, acc[21]);
                    acc[22] = fmaf(xk, w5.z, acc[22]);
                    acc[23] = fmaf(xk, w5.w, acc[23]);
                }
            }

            // store prefetched tile into the other buffer
            if (pf) {
                float* xd = Xsh[cur ^ 1];
                *reinterpret_cast<float4*>(xd + (r0 +  0) * 20 + (dp << 2)) = xs0;
                *reinterpret_cast<float4*>(xd + (r0 + 32) * 20 + (dp << 2)) = xs1;
                *reinterpret_cast<float4*>(xd + (r0 + 64) * 20 + (dp << 2)) = xs2;
                *reinterpret_cast<float4*>(xd + (r0 + 96) * 20 + (dp << 2)) = xs3;
            }
            __syncthreads();           // STS visible; buffer swap safe
        }
    }

    float4* dst = reinterpret_cast<float4*>(g_pre + (size_t)(rowbase + tid) * 24);
#pragma unroll
    for (int j = 0; j < 6; j++)
        dst[j] = make_float4(acc[4 * j], acc[4 * j + 1], acc[4 * j + 2], acc[4 * j + 3]);
}

// tanh via degree-9 odd Taylor, valid |u| <= 0.52 (err <= ~7e-6)
__device__ __forceinline__ float tanh_poly(float u) {
    float s = u * u;
    float p = fmaf(s, 0.021869488f, -0.053968254f);
    p = fmaf(s, p, 0.13333333f);
    p = fmaf(s, p, -0.33333333f);
    return fmaf(s * u, p, u);
}

// tanh via CF rational, one rcp; err <= ~2e-5 for |x| <= 2.2.
__device__ __forceinline__ float tanh_rat(float x) {
    float s = x * x;
    float num = fmaf(s, fmaf(s, 21.0f, 1260.0f), 10395.0f);
    float den = fmaf(s, fmaf(s, s + 210.0f, 4725.0f), 10395.0f);
    float r;
    asm("rcp.approx.f32 %0, %1;" : "=f"(r) : "f"(den));
    return x * num * r;
}

// ---------------------------------------------------------------------------
// K2: LSTM scan (R7, unchanged — 20.3us proven). grid 32 x 128.
// ---------------------------------------------------------------------------
__global__ void __launch_bounds__(128, 1) k2_scan(
    const float* __restrict__ Wf, const float* __restrict__ Wi,
    const float* __restrict__ Wu, const float* __restrict__ Wo,
    float* __restrict__ out)
{
    __shared__ float ps[TT * 192];    // 48KB : [t][bloc(8)][gate][q]

    const int tid = threadIdx.x;
    const int b0  = blockIdx.x << 3;

    {
        const float4* src = reinterpret_cast<const float4*>(g_pre);
        float4* dst = reinterpret_cast<float4*>(ps);
#pragma unroll
        for (int k = 0; k < 24; k++) {
            int i = tid + (k << 7);
            int t = i / 48;
            int c = i - t * 48;
            dst[t * 48 + c] = src[(size_t)(t * BB + b0) * 6 + c];
        }
    }
    __syncthreads();
    if (tid >= 32) return;

    const int lane = tid;
    const int g    = lane & 3;
    const int bl   = lane >> 2;
    const int b    = b0 + bl;
    const float* Wg = (g == 0) ? Wf : (g == 1) ? Wi : (g == 2) ? Wu : Wo;

    float Wh[36];
#pragma unroll
    for (int j = 0; j < 6; j++)
#pragma unroll
        for (int q = 0; q < 6; q++)
            Wh[j * 6 + q] = __ldg(Wg + (DD + j) * 6 + q);

    float h[6], c[6];
#pragma unroll
    for (int q = 0; q < 6; q++) { h[q] = 0.0f; c[q] = 0.0f; }

    const float* pb = ps + bl * 24 + g * 6;
    const unsigned mask = 0xffffffffu;
    const int qb = lane & ~3;
    const bool isU = (g == 2);

#pragma unroll 2
    for (int t = 0; t < TT; t++) {
        const float2 p0 = *reinterpret_cast<const float2*>(pb + t * 192 + 0);
        const float2 p1 = *reinterpret_cast<const float2*>(pb + t * 192 + 2);
        const float2 p2 = *reinterpret_cast<const float2*>(pb + t * 192 + 4);
        float p[6] = { p0.x, p0.y, p1.x, p1.y, p2.x, p2.y };

        float a[6];
#pragma unroll
        for (int q = 0; q < 6; q++) {
            float u0 = fmaf(h[2], Wh[2 * 6 + q], fmaf(h[1], Wh[1 * 6 + q], fmaf(h[0], Wh[0 * 6 + q], p[q])));
            float u1 = fmaf(h[3], Wh[3 * 6 + q], fmaf(h[4], Wh[4 * 6 + q], h[5] * Wh[5 * 6 + q]));
            a[q] = u0 + u1;
        }

        float z[6];
#pragma unroll
        for (int q = 0; q < 6; q++) z[q] = __cosf(a[q]);

        float z01 = z[0] * z[1];
        float z23 = z[2] * z[3];
        float z45 = z[4] * z[5];
        float w[6];
        w[1] = z01;
        w[2] = z01 * z[2];
        w[3] = z01 * z23;
        w[4] = w[3] * z[4];
        w[5] = w[3] * z45;
        w[0] = z[1] * (z23 * z45);

        float v[6];
#pragma unroll
        for (int q = 0; q < 6; q++) {
            float tq  = tanh_poly(0.5f * w[q]);
            float vt  = __fdividef(tq + tq, fmaf(tq, tq, 1.0f));
            v[q] = isU ? vt : fmaf(0.5f, tq, 0.5f);
        }

#pragma unroll
        for (int q = 0; q < 6; q++) {
            float fq = __shfl_sync(mask, v[q], qb + 0);
            float iq = __shfl_sync(mask, v[q], qb + 1);
            float uq = __shfl_sync(mask, v[q], qb + 2);
            float oq = __shfl_sync(mask, v[q], qb + 3);
            float cn = fmaf(fq, c[q], iq * uq);
            c[q] = cn;
            h[q] = oq * tanh_rat(cn);      // |cn| <= 2.08 guaranteed
        }

        if (g == 0) {
            float* o0 = out + ((size_t)t * BB + b) * 6;
            *reinterpret_cast<float2*>(o0 + 0) = make_float2(h[0], h[1]);
            *reinterpret_cast<float2*>(o0 + 2) = make_float2(h[2], h[3]);
            *reinterpret_cast<float2*>(o0 + 4) = make_float2(h[4], h[5]);
        }
    }

    if (g == 0) {
        float* hx = out + (size_t)TT * BB * 6 + (size_t)b * 6;
        float* cx = hx + BB * 6;
        *reinterpret_cast<float2*>(hx + 0) = make_float2(h[0], h[1]);
        *reinterpret_cast<float2*>(hx + 2) = make_float2(h[2], h[3]);
        *reinterpret_cast<float2*>(hx + 4) = make_float2(h[4], h[5]);
        *reinterpret_cast<float2*>(cx + 0) = make_float2(c[0], c[1]);
        *reinterpret_cast<float2*>(cx + 2) = make_float2(c[2], c[3]);
        *reinterpret_cast<float2*>(cx + 4) = make_float2(c[4], c[5]);
    }
}

extern "C" void kernel_launch(void* const* d_in, const int* in_sizes, int n_in,
                              void* d_out, int out_size)
{
    const float* X   = (const float*)d_in[0];
    const float* Wf  = (const float*)d_in[1];
    const float* bf  = (const float*)d_in[2];
    const float* Wi  = (const float*)d_in[3];
    const float* bi  = (const float*)d_in[4];
    const float* Wu  = (const float*)d_in[5];
    const float* bu  = (const float*)d_in[6];
    const float* Wo  = (const float*)d_in[7];
    const float* bo  = (const float*)d_in[8];
    const float* thf = (const float*)d_in[9];
    const float* thi = (const float*)d_in[10];
    const float* thu = (const float*)d_in[11];
    const float* tho = (const float*)d_in[12];
    float* out = (float*)d_out;

    k1_gemm<<<128, 128>>>(X, Wf, bf, Wi, bi, Wu, bu, Wo, bo, thf, thi, thu, tho);
    k2_scan<<<32, 128>>>(Wf, Wi, Wu, Wo, out);
}

// round 9
// speedup vs baseline: 1.1763x; 1.1763x over previous
#include <cuda_runtime.h>

#define TT 64
#define BB 256
#define DD 512

// pre-activations, K2-block-contiguous layout:
// g_pre2[bblk(32)][t(64)][bloc(8)][gate(4)][q(6)]
__device__ __align__(16) float g_pre2[TT * BB * 24];

// ---------------------------------------------------------------------------
// K1: pre[t,b,g,q] = inputs[t,b,:] @ Wg[:512,q] + bg[q] + theta_g[q]
// EXACT R2 kernel (best measured K1): grid 128 x 256; warp w: gate = w&3,
// row-half = w>>2; lane owns 2 adjacent rows; packed fma.rn.f32x2 accumulators.
// ---------------------------------------------------------------------------
__global__ void __launch_bounds__(256, 1) k1_gemm(
    const float* __restrict__ X,
    const float* __restrict__ Wf, const float* __restrict__ bf,
    const float* __restrict__ Wi, const float* __restrict__ bi,
    const float* __restrict__ Wu, const float* __restrict__ bu,
    const float* __restrict__ Wo, const float* __restrict__ bo,
    const float* __restrict__ thf, const float* __restrict__ thi,
    const float* __restrict__ thu, const float* __restrict__ tho)
{
    __shared__ float Wph[256 * 24];   // K-half of W, [dd][g*6+q]
    __shared__ float Xsh[32 * 130];   // x tile transposed [d][row]

    const int tid  = threadIdx.x;
    const int warp = tid >> 5;
    const int lane = tid & 31;
    const int gate = warp & 3;
    const int rloc = ((warp >> 2) << 6) + (lane << 1);   // block-local row (even)
    const int rowbase = blockIdx.x << 7;

    const float* bg = (gate == 0) ? bf  : (gate == 1) ? bi  : (gate == 2) ? bu  : bo;
    const float* tg = (gate == 0) ? thf : (gate == 1) ? thi : (gate == 2) ? thu : tho;

    // packed accumulators: (q0,q1) (q2,q3) (q4,q5) for each of 2 rows
    unsigned long long a0[3], a1[3];
#pragma unroll
    for (int p = 0; p < 3; p++) {
        float blo = __ldg(bg + 2 * p + 0) + __ldg(tg + 2 * p + 0);
        float bhi = __ldg(bg + 2 * p + 1) + __ldg(tg + 2 * p + 1);
        unsigned long long bp;
        asm("mov.b64 %0, {%1, %2};" : "=l"(bp) : "f"(blo), "f"(bhi));
        a0[p] = bp;
        a1[p] = bp;
    }

    const int cc = tid & 7;   // d-group for staging
    const int rr = tid >> 3;  // row for staging

    for (int kh = 0; kh < 2; kh++) {
        __syncthreads();  // prior compute done before Wph overwrite
#pragma unroll
        for (int k = 0; k < 24; k++) {
            int idx = tid + (k << 8);          // dd*24 + col
            int dd  = idx / 24;
            int col = idx - dd * 24;
            int g2  = col / 6;
            int q2  = col - g2 * 6;
            const float* Ws = (g2 == 0) ? Wf : (g2 == 1) ? Wi : (g2 == 2) ? Wu : Wo;
            Wph[idx] = Ws[((kh << 8) + dd) * 6 + q2];
        }
        for (int tile = 0; tile < 8; tile++) {
            const int d0 = (kh << 8) + (tile << 5);
            __syncthreads();
#pragma unroll
            for (int p = 0; p < 4; p++) {
                int r = rr + (p << 5);
                const float4 v = *reinterpret_cast<const float4*>(
                    X + (size_t)(rowbase + r) * DD + d0 + (cc << 2));
                Xsh[((cc << 2) + 0) * 130 + r] = v.x;
                Xsh[((cc << 2) + 1) * 130 + r] = v.y;
                Xsh[((cc << 2) + 2) * 130 + r] = v.z;
                Xsh[((cc << 2) + 3) * 130 + r] = v.w;
            }
            __syncthreads();
#pragma unroll
            for (int d = 0; d < 32; d++) {
                const int dd = (tile << 5) + d;
                const unsigned long long* wp =
                    reinterpret_cast<const unsigned long long*>(&Wph[dd * 24 + gate * 6]);
                const unsigned long long w01 = wp[0];
                const unsigned long long w23 = wp[1];
                const unsigned long long w45 = wp[2];
                const float2 x2 = *reinterpret_cast<const float2*>(&Xsh[d * 130 + rloc]);
                unsigned long long xr0, xr1;
                asm("mov.b64 %0, {%1, %1};" : "=l"(xr0) : "f"(x2.x));
                asm("mov.b64 %0, {%1, %1};" : "=l"(xr1) : "f"(x2.y));
                asm("fma.rn.f32x2 %0, %1, %2, %0;" : "+l"(a0[0]) : "l"(w01), "l"(xr0));
                asm("fma.rn.f32x2 %0, %1, %2, %0;" : "+l"(a0[1]) : "l"(w23), "l"(xr0));
                asm("fma.rn.f32x2 %0, %1, %2, %0;" : "+l"(a0[2]) : "l"(w45), "l"(xr0));
                asm("fma.rn.f32x2 %0, %1, %2, %0;" : "+l"(a1[0]) : "l"(w01), "l"(xr1));
                asm("fma.rn.f32x2 %0, %1, %2, %0;" : "+l"(a1[1]) : "l"(w23), "l"(xr1));
                asm("fma.rn.f32x2 %0, %1, %2, %0;" : "+l"(a1[2]) : "l"(w45), "l"(xr1));
            }
        }
    }

    // row = t*BB + b ; store to block-contiguous layout
    const int t = rowbase >> 8;
    const int b = (rowbase & 255) + rloc;       // even; b+1 shares b>>3
    float* dst = g_pre2 + ((size_t)((b >> 3) * 64 + t) * 192) + (b & 7) * 24 + gate * 6;
    unsigned long long* d64 = reinterpret_cast<unsigned long long*>(dst);
    d64[0] = a0[0]; d64[1] = a0[1]; d64[2] = a0[2];
    unsigned long long* e64 = reinterpret_cast<unsigned long long*>(dst + 24);
    e64[0] = a1[0]; e64[1] = a1[1]; e64[2] = a1[2];
}

// tanh via CF rational x*(10395+1260 s+21 s^2)/(10395+4725 s+210 s^2+s^3),
// one rcp; err <= ~2e-5 for |x| <= 2.2 (|c| <= 2.08 guaranteed by gate bounds)
__device__ __forceinline__ float tanh_rat(float x) {
    float s = x * x;
    float num = fmaf(s, fmaf(s, 21.0f, 1260.0f), 10395.0f);
    float den = fmaf(s, fmaf(s, s + 210.0f, 4725.0f), 10395.0f);
    float r;
    asm("rcp.approx.f32 %0, %1;" : "=f"(r) : "f"(den));
    return x * num * r;
}

// ---------------------------------------------------------------------------
// K2: LSTM scan — EXACT R2 kernel (best measured: 18.0us) with ONE change:
// tanh(c) via single-rcp rational instead of exp(2c) form.
// grid 32 x 128; warps stage 48KB of pre; warp 0 scans.
// lane = (batch-in-block<<2)|gate ; h,c replicated across the 4 gate lanes.
// ---------------------------------------------------------------------------
__global__ void __launch_bounds__(128, 1) k2_scan(
    const float* __restrict__ Wf, const float* __restrict__ Wi,
    const float* __restrict__ Wu, const float* __restrict__ Wo,
    float* __restrict__ out)
{
    __shared__ float ps[TT * 192];    // 48KB : [t][bloc(8)][gate][q]

    const int tid = threadIdx.x;

    // cooperative bulk load (coalesced float4)
    {
        const float4* src = reinterpret_cast<const float4*>(g_pre2 + (size_t)blockIdx.x * (TT * 192));
        float4* dst = reinterpret_cast<float4*>(ps);
#pragma unroll
        for (int i = 0; i < (TT * 192) / 4 / 128; i++)
            dst[tid + i * 128] = src[tid + i * 128];
    }
    __syncthreads();
    if (tid >= 32) return;

    const int lane = tid;
    const int g    = lane & 3;
    const int bl   = lane >> 2;
    const int b    = (blockIdx.x << 3) + bl;
    const float* Wg = (g == 0) ? Wf : (g == 1) ? Wi : (g == 2) ? Wu : Wo;

    float Wh[36];
#pragma unroll
    for (int j = 0; j < 6; j++)
#pragma unroll
        for (int q = 0; q < 6; q++)
            Wh[j * 6 + q] = __ldg(Wg + (DD + j) * 6 + q);

    float h[6], c[6];
#pragma unroll
    for (int q = 0; q < 6; q++) { h[q] = 0.0f; c[q] = 0.0f; }

    const float* pb = ps + bl * 24 + g * 6;
    const unsigned mask = 0xffffffffu;
    const int qb = lane & ~3;
    const bool isU = (g == 2);
    const float cmul = isU ? -2.0f : -1.0f;   // exp argument scale

#pragma unroll 2
    for (int t = 0; t < TT; t++) {
        const float2 p0 = *reinterpret_cast<const float2*>(pb + t * 192 + 0);
        const float2 p1 = *reinterpret_cast<const float2*>(pb + t * 192 + 2);
        const float2 p2 = *reinterpret_cast<const float2*>(pb + t * 192 + 4);
        float p[6] = { p0.x, p0.y, p1.x, p1.y, p2.x, p2.y };

        // a[q] = p[q] + h @ Wh  -- two parallel partials, then add
        float a[6];
#pragma unroll
        for (int q = 0; q < 6; q++) {
            float u0 = fmaf(h[0], Wh[0 * 6 + q], fmaf(h[1], Wh[1 * 6 + q], fmaf(h[2], Wh[2 * 6 + q], p[q])));
            float u1 = fmaf(h[3], Wh[3 * 6 + q], fmaf(h[4], Wh[4 * 6 + q], h[5] * Wh[5 * 6 + q]));
            a[q] = u0 + u1;
        }

        float z[6];
#pragma unroll
        for (int q = 0; q < 6; q++) z[q] = __cosf(a[q]);

        // prefix products (tree form)
        float z01 = z[0] * z[1];
        float z23 = z[2] * z[3];
        float z45 = z[4] * z[5];
        float w[6];
        w[1] = z01;
        w[2] = z01 * z[2];
        w[3] = z01 * z23;
        w[4] = w[3] * z[4];
        w[5] = w[3] * z45;
        w[0] = z[1] * (z23 * z45);

        // f,i,o: sigmoid(w) ; u: tanh(w) = 2*sigmoid(2w)-1   (exp-based, proven)
        float v[6];
#pragma unroll
        for (int q = 0; q < 6; q++) {
            float e  = __expf(cmul * w[q]);
            float s  = __fdividef(1.0f, 1.0f + e);
            v[q] = isU ? fmaf(2.0f, s, -1.0f) : s;
        }

        // gather the 4 gates' values and update (replicated)
#pragma unroll
        for (int q = 0; q < 6; q++) {
            float fq = __shfl_sync(mask, v[q], qb + 0);
            float iq = __shfl_sync(mask, v[q], qb + 1);
            float uq = __shfl_sync(mask, v[q], qb + 2);
            float oq = __shfl_sync(mask, v[q], qb + 3);
            float cn = fmaf(fq, c[q], iq * uq);
            c[q] = cn;
            h[q] = oq * tanh_rat(cn);          // <- the one change vs R2
        }

        if (g == 0) {
            float* o0 = out + ((size_t)t * BB + b) * 6;
            *reinterpret_cast<float2*>(o0 + 0) = make_float2(h[0], h[1]);
            *reinterpret_cast<float2*>(o0 + 2) = make_float2(h[2], h[3]);
            *reinterpret_cast<float2*>(o0 + 4) = make_float2(h[4], h[5]);
        }
    }

    if (g == 0) {
        float* hx = out + (size_t)TT * BB * 6 + (size_t)b * 6;
        float* cx = hx + BB * 6;
        *reinterpret_cast<float2*>(hx + 0) = make_float2(h[0], h[1]);
        *reinterpret_cast<float2*>(hx + 2) = make_float2(h[2], h[3]);
        *reinterpret_cast<float2*>(hx + 4) = make_float2(h[4], h[5]);
        *reinterpret_cast<float2*>(cx + 0) = make_float2(c[0], c[1]);
        *reinterpret_cast<float2*>(cx + 2) = make_float2(c[2], c[3]);
        *reinterpret_cast<float2*>(cx + 4) = make_float2(c[4], c[5]);
    }
}

extern "C" void kernel_launch(void* const* d_in, const int* in_sizes, int n_in,
                              void* d_out, int out_size)
{
    const float* X   = (const float*)d_in[0];
    const float* Wf  = (const float*)d_in[1];
    const float* bf  = (const float*)d_in[2];
    const float* Wi  = (const float*)d_in[3];
    const float* bi  = (const float*)d_in[4];
    const float* Wu  = (const float*)d_in[5];
    const float* bu  = (const float*)d_in[6];
    const float* Wo  = (const float*)d_in[7];
    const float* bo  = (const float*)d_in[8];
    const float* thf = (const float*)d_in[9];
    const float* thi = (const float*)d_in[10];
    const float* thu = (const float*)d_in[11];
    const float* tho = (const float*)d_in[12];
    float* out = (float*)d_out;

    k1_gemm<<<128, 256>>>(X, Wf, bf, Wi, bi, Wu, bu, Wo, bo, thf, thi, thu, tho);
    k2_scan<<<32, 128>>>(Wf, Wi, Wu, Wo, out);
}